// round 11
// baseline (speedup 1.0000x reference)
#include <cuda_runtime.h>
#include <cstdint>

// ResBlock_71021579207010 — fused binarized ResBlock (B=32, T=8192, C=F=128, K=2, dil=16).
//
// Algebra (verified R4/R5/R8/R10, rel_err ~2e-7):
//   shortcut[b,t,f] = sum_c sign(x[b,t,c]) * sign(w_sc[0,c,f])           (exact binary dot)
//   conv2 input = ste_sign(relu(...)) == +1  =>  conv2 out constant per (t<16 | t>=16)
//   conv1/bn1/w1/beta1/mean1/var1 are dead.
//   out = relu( shortcut + relu(bn2(const)) )
//
// R11 vs R10 (46.1us main; DRAM 58%, alu 44%, issue 48%, occ 37.5% — NOTHING saturated,
// invariant across three different schedules => concurrency-limited at 32 warps/SM):
//   * __launch_bounds__(256,5): regs<=48 -> 5 blocks/SM = 40 resident warps (+25%)
//   * prefetch ring dropped (measured zero effect R5->R8); instead 2 rows per loop
//     iteration: two independent LDG.128 issued together, then two compute bodies
//   * persistent grid = 148*5 = 740 blocks (one full wave at the new residency)

#define T_LEN   8192
#define C_DIM   128
#define F_DIM   128
#define B_DIM   32
#define ROWS_TOTAL (B_DIM * T_LEN)      // 262144

#define NUM_SMS        148
#define BLOCKS_PER_SM  5
#define BLOCK_THREADS  256
#define WARPS_PER_BLOCK (BLOCK_THREADS / 32)             // 8
#define GRID_BLOCKS    (NUM_SMS * BLOCKS_PER_SM)         // 740
#define TOTAL_WARPS    (GRID_BLOCKS * WARPS_PER_BLOCK)   // 5920
#define ITERS          46                                // even, 46*5920 >= 262144

__device__ uint4 g_wsc[F_DIM];    // packed sign(w_sc): word k bit l <-> channel c = 4*l + k
__device__ float g_clo[F_DIM];    // 128 + relu(bn2(S1))       for t <  16
__device__ float g_chi[F_DIM];    // 128 + relu(bn2(S0+S1))    for t >= 16

// One warp per output channel f; packing uses the SAME ballot construction the
// main kernel applies to x, so bit conventions match by design.
__global__ void precompute_kernel(const float* __restrict__ w2,    // [2,128,128]
                                  const float* __restrict__ w_sc,  // [1,128,128]
                                  const float* __restrict__ beta2,
                                  const float* __restrict__ mean2,
                                  const float* __restrict__ var2) {
    const int f = blockIdx.x;          // 0..127
    const int l = threadIdx.x;         // lane 0..31

    // word k, bit l  <->  channel c = 4*l + k
    unsigned p0 = __ballot_sync(0xffffffffu, w_sc[(4 * l + 0) * F_DIM + f] < 0.0f);
    unsigned p1 = __ballot_sync(0xffffffffu, w_sc[(4 * l + 1) * F_DIM + f] < 0.0f);
    unsigned p2 = __ballot_sync(0xffffffffu, w_sc[(4 * l + 2) * F_DIM + f] < 0.0f);
    unsigned p3 = __ballot_sync(0xffffffffu, w_sc[(4 * l + 3) * F_DIM + f] < 0.0f);

    // Column sums of sign(w2[k,:,f]): count negatives via ballot popc, 4 chans/lane.
    int n0 = 0, n1 = 0;
    #pragma unroll
    for (int j = 0; j < 4; ++j) {
        int c = 4 * l + j;
        unsigned b0 = __ballot_sync(0xffffffffu, w2[(0 * C_DIM + c) * F_DIM + f] < 0.0f);
        unsigned b1 = __ballot_sync(0xffffffffu, w2[(1 * C_DIM + c) * F_DIM + f] < 0.0f);
        n0 += __popc(b0);
        n1 += __popc(b1);
    }

    if (l == 0) {
        g_wsc[f] = make_uint4(p0, p1, p2, p3);
        float S0 = (float)(C_DIM - 2 * n0);
        float S1 = (float)(C_DIM - 2 * n1);
        float inv = rsqrtf(var2[f] + 1e-3f);
        float lo  = (S1      - mean2[f]) * inv + beta2[f];
        float hi  = (S0 + S1 - mean2[f]) * inv + beta2[f];
        // pre-bias by +C_DIM: out = relu((C_DIM - 2*neq) + relu(bn)) = relu(fma(neq,-2,cst))
        g_clo[f] = fmaxf(lo, 0.0f) + (float)C_DIM;
        g_chi[f] = fmaxf(hi, 0.0f) + (float)C_DIM;
    }
}

__global__ __launch_bounds__(BLOCK_THREADS, BLOCKS_PER_SM)
void resblock_main_kernel(const float* __restrict__ x, float* __restrict__ out) {
    const int lane  = threadIdx.x & 31;
    const int warp  = threadIdx.x >> 5;
    const int gwarp = blockIdx.x * WARPS_PER_BLOCK + warp;   // 0..5919

    // Per-thread weights/constants in registers (f = 4*lane+j, loop-invariant).
    const uint4* wp = (const uint4*)g_wsc + 4 * lane;
    const uint4 wb0 = wp[0];
    const uint4 wb1 = wp[1];
    const uint4 wb2 = wp[2];
    const uint4 wb3 = wp[3];
    const float4 chi = ((const float4*)g_chi)[lane];
    const float4 clo = ((const float4*)g_clo)[lane];

    const float4* __restrict__ src = (const float4*)x  + lane;   // + r*32 per row
    float4*       __restrict__ dst = (float4*)     out + lane;

    #pragma unroll 2
    for (int i = 0; i < ITERS; i += 2) {
        const int r0 = gwarp + i * TOTAL_WARPS;
        const int r1 = r0 + TOTAL_WARPS;
        const bool v0ok = (r0 < ROWS_TOTAL);
        const bool v1ok = (r1 < ROWS_TOTAL);

        // Two independent loads issued back-to-back (MLP=2 per warp).
        float4 v0, v1;
        if (v0ok) v0 = __ldcs(src + (size_t)r0 * (C_DIM / 4));
        if (v1ok) v1 = __ldcs(src + (size_t)r1 * (C_DIM / 4));

        if (v0ok) {
            const unsigned a0 = __ballot_sync(0xffffffffu, v0.x < 0.0f);
            const unsigned a1 = __ballot_sync(0xffffffffu, v0.y < 0.0f);
            const unsigned a2 = __ballot_sync(0xffffffffu, v0.z < 0.0f);
            const unsigned a3 = __ballot_sync(0xffffffffu, v0.w < 0.0f);
            const int n0 = __popc(a0 ^ wb0.x) + __popc(a1 ^ wb0.y) + __popc(a2 ^ wb0.z) + __popc(a3 ^ wb0.w);
            const int n1 = __popc(a0 ^ wb1.x) + __popc(a1 ^ wb1.y) + __popc(a2 ^ wb1.z) + __popc(a3 ^ wb1.w);
            const int n2 = __popc(a0 ^ wb2.x) + __popc(a1 ^ wb2.y) + __popc(a2 ^ wb2.z) + __popc(a3 ^ wb2.w);
            const int n3 = __popc(a0 ^ wb3.x) + __popc(a1 ^ wb3.y) + __popc(a2 ^ wb3.z) + __popc(a3 ^ wb3.w);
            const float4 cst = ((r0 & (T_LEN - 1)) >= 16) ? chi : clo;
            float4 o;
            o.x = fmaxf(fmaf((float)n0, -2.0f, cst.x), 0.0f);
            o.y = fmaxf(fmaf((float)n1, -2.0f, cst.y), 0.0f);
            o.z = fmaxf(fmaf((float)n2, -2.0f, cst.z), 0.0f);
            o.w = fmaxf(fmaf((float)n3, -2.0f, cst.w), 0.0f);
            __stcs(dst + (size_t)r0 * (F_DIM / 4), o);
        }

        if (v1ok) {
            const unsigned a0 = __ballot_sync(0xffffffffu, v1.x < 0.0f);
            const unsigned a1 = __ballot_sync(0xffffffffu, v1.y < 0.0f);
            const unsigned a2 = __ballot_sync(0xffffffffu, v1.z < 0.0f);
            const unsigned a3 = __ballot_sync(0xffffffffu, v1.w < 0.0f);
            const int n0 = __popc(a0 ^ wb0.x) + __popc(a1 ^ wb0.y) + __popc(a2 ^ wb0.z) + __popc(a3 ^ wb0.w);
            const int n1 = __popc(a0 ^ wb1.x) + __popc(a1 ^ wb1.y) + __popc(a2 ^ wb1.z) + __popc(a3 ^ wb1.w);
            const int n2 = __popc(a0 ^ wb2.x) + __popc(a1 ^ wb2.y) + __popc(a2 ^ wb2.z) + __popc(a3 ^ wb2.w);
            const int n3 = __popc(a0 ^ wb3.x) + __popc(a1 ^ wb3.y) + __popc(a2 ^ wb3.z) + __popc(a3 ^ wb3.w);
            const float4 cst = ((r1 & (T_LEN - 1)) >= 16) ? chi : clo;
            float4 o;
            o.x = fmaxf(fmaf((float)n0, -2.0f, cst.x), 0.0f);
            o.y = fmaxf(fmaf((float)n1, -2.0f, cst.y), 0.0f);
            o.z = fmaxf(fmaf((float)n2, -2.0f, cst.z), 0.0f);
            o.w = fmaxf(fmaf((float)n3, -2.0f, cst.w), 0.0f);
            __stcs(dst + (size_t)r1 * (F_DIM / 4), o);
        }
    }
}

extern "C" void kernel_launch(void* const* d_in, const int* in_sizes, int n_in,
                              void* d_out, int out_size) {
    // metadata order: x, w1, w2, w_sc, beta1, mean1, var1, beta2, mean2, var2
    const float* x     = (const float*)d_in[0];
    const float* w2    = (const float*)d_in[2];
    const float* w_sc  = (const float*)d_in[3];
    const float* beta2 = (const float*)d_in[7];
    const float* mean2 = (const float*)d_in[8];
    const float* var2  = (const float*)d_in[9];
    float* out = (float*)d_out;

    precompute_kernel<<<F_DIM, 32>>>(w2, w_sc, beta2, mean2, var2);
    resblock_main_kernel<<<GRID_BLOCKS, BLOCK_THREADS>>>(x, out);
}